// round 1
// baseline (speedup 1.0000x reference)
#include <cuda_runtime.h>

// SRLEmbeddings: B=16,S=32,L=256,D=768,P=16,T=4, PAD=1
// Inputs (metadata order):
//   0 sentence_ids            int32  [B,S,L]
//   1 sentence_attention_masks int32 [B,S,L]
//   2 predicate_ids           int32  [B,S,P,T]
//   3 arg0_ids                int32  [B,S,P,T]
//   4 arg1_ids                int32  [B,S,P,T]
//   5 token_embeddings        fp32   [B,S,L,D]
// Output (fp32, concatenated):
//   sentence_avg [B,S,D] | predicate [B,S,P,D] | arg0 [B,S,P,D] | arg1 [B,S,P,D]

#define NB 16
#define NS 32
#define NL 256
#define ND 768
#define NP 16
#define NT 4
#define NPAIR 48          // 3 arg types * 16 predicates
#define PAD_ID 1
#define NTHREADS 768

// smem layout sizes (bytes)
//   acc   : NPAIR*ND*4       = 147456
//   cnt_s : NPAIR*NL         =  12288
//   rm    : NL*2*4           =   2048
//   sid_s : NL*4             =   1024
//   af    : NL*4             =   1024
//   span_s: NPAIR*NT*4       =    768
//   den_s : NPAIR*4          =    192
//   tokcnt: 4
#define SMEM_BYTES (147456 + 12288 + 2048 + 1024 + 1024 + 768 + 192 + 16)

__global__ __launch_bounds__(NTHREADS, 1)
void srl_kernel(const int* __restrict__ sent_ids,
                const int* __restrict__ attn,
                const int* __restrict__ pred_ids,
                const int* __restrict__ arg0_ids,
                const int* __restrict__ arg1_ids,
                const float* __restrict__ emb,
                float* __restrict__ out)
{
    extern __shared__ char smem_raw[];
    float*         acc    = (float*)smem_raw;                       // [NPAIR][ND]
    unsigned char* cnt_s  = (unsigned char*)(acc + NPAIR * ND);     // [NPAIR][NL]
    unsigned*      rm     = (unsigned*)(cnt_s + NPAIR * NL);        // [NL][2] bitmask of matching pairs
    int*           sid_s  = (int*)(rm + 2 * NL);                    // [NL]
    float*         af     = (float*)(sid_s + NL);                   // [NL] attn as 0/1 float
    int*           span_s = (int*)(af + NL);                        // [NPAIR][NT]
    int*           den_s  = (int*)(span_s + NPAIR * NT);            // [NPAIR]
    int*           tokcnt = den_s + NPAIR;                          // [1]

    const int bs  = blockIdx.x;        // b*NS + s
    const int tid = threadIdx.x;       // 0..767 == column d

    // ---- init ----
    #pragma unroll
    for (int i = 0; i < NPAIR; i++) acc[i * ND + tid] = 0.0f;
    if (tid < NPAIR) den_s[tid] = 0;
    if (tid == 0)    tokcnt[0]  = 0;
    if (tid < 2 * NL) rm[tid] = 0u;

    // ---- load sentence ids / attention ----
    if (tid < NL) {
        sid_s[tid] = sent_ids[bs * NL + tid];
        int a = attn[bs * NL + tid];
        af[tid] = (a != 0) ? 1.0f : 0.0f;
        if (a != 0) atomicAdd(tokcnt, 1);
    }
    // ---- load span ids: 3 args * P * T = 192 ints ----
    if (tid < NPAIR * NT) {
        int arg = tid / (NP * NT);
        int rem = tid % (NP * NT);
        const int* src = (arg == 0) ? pred_ids : ((arg == 1) ? arg0_ids : arg1_ids);
        span_s[tid] = src[bs * NP * NT + rem];
    }
    __syncthreads();

    // ---- phase 1: match counts cnt[pair][l], row bitmask, den[pair] ----
    for (int e = tid; e < NPAIR * NL; e += NTHREADS) {
        int pair = e >> 8;          // e / 256
        int l    = e & (NL - 1);
        int c = 0;
        if (af[l] != 0.0f) {
            int sid = sid_s[l];
            #pragma unroll
            for (int t = 0; t < NT; t++) {
                int v = span_s[pair * NT + t];
                c += (v == sid && v != PAD_ID) ? 1 : 0;
            }
        }
        cnt_s[pair * NL + l] = (unsigned char)c;
        if (c) {
            atomicOr(&rm[2 * l + (pair >> 5)], 1u << (pair & 31));
            atomicAdd(&den_s[pair], c);
        }
    }
    __syncthreads();

    // ---- phase 2: stream the L x D tile once ----
    const float* ebase = emb + (size_t)bs * NL * ND + tid;
    float sacc = 0.0f;

    for (int l0 = 0; l0 < NL; l0 += 8) {
        float v[8];
        #pragma unroll
        for (int k = 0; k < 8; k++)
            v[k] = __ldg(ebase + (size_t)(l0 + k) * ND);

        #pragma unroll
        for (int k = 0; k < 8; k++) {
            int l = l0 + k;
            sacc = fmaf(af[l], v[k], sacc);
            unsigned w0 = rm[2 * l];
            unsigned w1 = rm[2 * l + 1];
            while (w0) {
                int pr = __ffs(w0) - 1; w0 &= (w0 - 1);
                acc[pr * ND + tid] = fmaf((float)cnt_s[pr * NL + l], v[k], acc[pr * ND + tid]);
            }
            while (w1) {
                int pr = __ffs(w1) - 1; w1 &= (w1 - 1);
                int pp = pr + 32;
                acc[pp * ND + tid] = fmaf((float)cnt_s[pp * NL + l], v[k], acc[pp * ND + tid]);
            }
        }
    }
    // Each thread only touches its own column of acc -> no cross-thread sync needed.

    // ---- epilogue ----
    // sentence average
    float tc = (float)tokcnt[0];
    tc = fmaxf(tc, 1.0f);
    out[(size_t)bs * ND + tid] = sacc / tc;

    // span outputs: pred | arg0 | arg1, each [B,S,P,D]
    float* outp = out + (size_t)NB * NS * ND;
    #pragma unroll 4
    for (int pair = 0; pair < NPAIR; pair++) {
        int arg = pair >> 4;
        int p   = pair & 15;
        int den = den_s[pair];
        float val = 0.0f;
        if (den > 0) val = acc[pair * ND + tid] / (float)den;
        size_t off = (size_t)arg * NB * NS * NP * ND
                   + (size_t)bs * NP * ND
                   + (size_t)p * ND + tid;
        outp[off] = val;
    }
}

extern "C" void kernel_launch(void* const* d_in, const int* in_sizes, int n_in,
                              void* d_out, int out_size)
{
    const int*   sent_ids = (const int*)d_in[0];
    const int*   attn     = (const int*)d_in[1];
    const int*   pred_ids = (const int*)d_in[2];
    const int*   arg0_ids = (const int*)d_in[3];
    const int*   arg1_ids = (const int*)d_in[4];
    const float* emb      = (const float*)d_in[5];
    float*       out      = (float*)d_out;

    cudaFuncSetAttribute(srl_kernel, cudaFuncAttributeMaxDynamicSharedMemorySize, SMEM_BYTES);

    dim3 grid(NB * NS);
    dim3 block(NTHREADS);
    srl_kernel<<<grid, block, SMEM_BYTES>>>(sent_ids, attn, pred_ids, arg0_ids,
                                            arg1_ids, emb, out);
}